// round 4
// baseline (speedup 1.0000x reference)
#include <cuda_runtime.h>
#include <cuda_fp16.h>

// GraphSAGENet: 50000 nodes, 800000 edges, feats 96 -> 48 -> 48 -> 48 -> 1
constexpr int NN = 50000;
constexpr int NE = 800000;
constexpr int F0 = 96;
constexpr int H  = 48;
constexpr int GFILL  = NE / 256;               // 3125
constexpr int GNODE8 = (NN * 8 + 255) / 256;   // 1563 (8 threads per node)

// Scratch (static device globals; zero-initialized at module load).
// g_deg and g_alloc are re-zeroed at the tail of the last kernel each call.
__device__ uint4 g_y0[NN * 6];   // fp16 y rows: 48 halfs = 96 B = 6 uint4
__device__ uint4 g_y1[NN * 6];
__device__ float g_h0[NN * H];
__device__ float g_h1[NN * H];
__device__ int   g_deg[NN];
__device__ int   g_alloc;
__device__ int2  g_seg[NN];      // (start, deg)
__device__ float g_dinv[NN];
__device__ int   g_cursor[NN];
__device__ int   g_col[NE];

// fp16 pack/unpack helpers
__device__ __forceinline__ unsigned pack2(float a, float b) {
    __half2 h = __float22half2_rn(make_float2(a, b));
    return *reinterpret_cast<unsigned*>(&h);
}
__device__ __forceinline__ float2 up2(unsigned u) {
    __half2 h = *reinterpret_cast<__half2*>(&u);
    return __half22float2(h);
}
__device__ __forceinline__ void acc_row(float* acc, uint4 a, uint2 b) {
    float2 f;
    f = up2(a.x); acc[0] += f.x; acc[1]  += f.y;
    f = up2(a.y); acc[2] += f.x; acc[3]  += f.y;
    f = up2(a.z); acc[4] += f.x; acc[5]  += f.y;
    f = up2(a.w); acc[6] += f.x; acc[7]  += f.y;
    f = up2(b.x); acc[8] += f.x; acc[9]  += f.y;
    f = up2(b.y); acc[10] += f.x; acc[11] += f.y;
}

// Feature mapping: lane t owns feats [8t..8t+7] (slots 0..7)
//                  and feats [32+4t..32+4t+3] (slots 8..11)

// ---------------------------------------------------------------------------
// degree histogram (g_deg zero on entry; tail of k_layer<PRED> re-zeroes it)
// ---------------------------------------------------------------------------
__global__ void k_count(const int* __restrict__ dst) {
    int e = blockIdx.x * 256 + threadIdx.x;
    atomicAdd(&g_deg[dst[e]], 1);
}

// ---------------------------------------------------------------------------
// segment allocation: start = atomicAdd(g_alloc, deg), warp-aggregated.
// ---------------------------------------------------------------------------
__global__ void k_alloc() {
    int i = blockIdx.x * 256 + threadIdx.x;
    int lane = threadIdx.x & 31;
    int d = (i < NN) ? g_deg[i] : 0;

    int s = d;
#pragma unroll
    for (int off = 1; off < 32; off <<= 1) {
        int t = __shfl_up_sync(0xffffffffu, s, off);
        if (lane >= off) s += t;
    }
    int total = __shfl_sync(0xffffffffu, s, 31);
    int base = 0;
    if (lane == 31) base = atomicAdd(&g_alloc, total);
    base = __shfl_sync(0xffffffffu, base, 31);
    int start = base + s - d;

    if (i < NN) {
        g_seg[i] = make_int2(start, d);
        g_cursor[i] = start;
        g_dinv[i] = 1.0f / (float)(d > 1 ? d : 1);
    }
}

// ---------------------------------------------------------------------------
// Fused: blocks [0,GFILL) fill CSR cols; blocks [GFILL,GFILL+GNODE8):
// y0 = x @ W_neigh0 (fp16 out), 8 lanes/node, k-split across quads.
// ---------------------------------------------------------------------------
__global__ void __launch_bounds__(256, 4)
k_fill_gemm(const int* __restrict__ src,
            const int* __restrict__ dst,
            const float* __restrict__ x,
            const float* __restrict__ W,
            uint4* __restrict__ yout) {
    __shared__ float sW[F0 * H];

    if (blockIdx.x < GFILL) {
        int e = blockIdx.x * 256 + threadIdx.x;
        int pos = atomicAdd(&g_cursor[dst[e]], 1);
        g_col[pos] = src[e];
        return;
    }

    for (int i = threadIdx.x; i < F0 * H; i += 256) sW[i] = W[i];
    __syncthreads();

    int idx = (blockIdx.x - GFILL) * 256 + threadIdx.x;
    int g = idx >> 3;
    int l = idx & 7;
    int t = l & 3;
    int q = l >> 2;
    bool valid = g < NN;
    int n = valid ? g : NN - 1;

    float acc[12];
#pragma unroll
    for (int j = 0; j < 12; j++) acc[j] = 0.0f;

    // k-half for this quad: [q*48, q*48+48)
    const float4* xr = reinterpret_cast<const float4*>(x + (size_t)n * F0) + q * 12;
#pragma unroll
    for (int k0 = 0; k0 < 12; k0++) {
        float4 xv = xr[k0];
        float xs[4] = {xv.x, xv.y, xv.z, xv.w};
        int kb = q * 48 + k0 * 4;
#pragma unroll
        for (int kk = 0; kk < 4; kk++) {
            const float* wr = &sW[(kb + kk) * H];
#pragma unroll
            for (int j = 0; j < 8; j++) acc[j] += xs[kk] * wr[t * 8 + j];
#pragma unroll
            for (int j = 0; j < 4; j++) acc[8 + j] += xs[kk] * wr[32 + t * 4 + j];
        }
    }
#pragma unroll
    for (int j = 0; j < 12; j++) acc[j] += __shfl_xor_sync(0xffffffffu, acc[j], 4);

    if (valid && q == 0) {
        uint4* row = yout + (size_t)g * 6;
        uint4 o;
        o.x = pack2(acc[0], acc[1]); o.y = pack2(acc[2], acc[3]);
        o.z = pack2(acc[4], acc[5]); o.w = pack2(acc[6], acc[7]);
        row[t] = o;
        reinterpret_cast<uint2*>(row + 4)[t] =
            make_uint2(pack2(acc[8], acc[9]), pack2(acc[10], acc[11]));
    }
}

// ---------------------------------------------------------------------------
// Fused layer, 8 lanes per node (octet = 2 quads):
//   gather: quads split the edge list (even/odd), combine via shfl_xor(4)
//   self GEMM: quads split k-dim, combine via shfl_xor(4)
//   !PRED: store h (q==0); y_out = h @ Wnext, quads split owner pairs
//   PRED : out[n] = h . wpred + bpred; tail: zero g_deg / g_alloc
// ---------------------------------------------------------------------------
template <int KSELF, bool PRED>
__global__ void __launch_bounds__(256, 4)
k_layer(const float* __restrict__ xin,
        const uint4* __restrict__ yin,
        const float* __restrict__ Ws,
        const float* __restrict__ bias,
        const float* __restrict__ Wn,   // [H*H] or [H] if PRED
        const float* __restrict__ bn,   // b_pred if PRED
        float* __restrict__ hout,       // null if PRED
        void* __restrict__ yout_) {     // uint4* y_next or float* out
    __shared__ float sWs[KSELF * H];
    __shared__ float sWn[PRED ? H : H * H];
    __shared__ float sb[H];
    for (int i = threadIdx.x; i < KSELF * H; i += 256) sWs[i] = Ws[i];
    for (int i = threadIdx.x; i < (PRED ? H : H * H); i += 256) sWn[i] = Wn[i];
    if (threadIdx.x < H) sb[threadIdx.x] = bias[threadIdx.x];
    __syncthreads();

    int gid = blockIdx.x * 256 + threadIdx.x;
    int g = gid >> 3;
    int l = gid & 7;
    int t = l & 3;
    int q = l >> 2;
    bool valid = g < NN;
    int n = valid ? g : NN - 1;
    int ob = (threadIdx.x & 31) & ~7;   // octet base lane

    float acc[12];
#pragma unroll
    for (int j = 0; j < 12; j++) acc[j] = 0.0f;

    // ---- gather over in-neighbors: quad q takes edges start+q, start+q+2, ...
    {
        int2 seg = g_seg[n];
        int e = seg.x + q;
        int end = seg.x + seg.y;
        for (; e + 2 < end; e += 4) {
            int s0 = g_col[e];
            int s1 = g_col[e + 2];
            const uint4* r0 = yin + (size_t)s0 * 6;
            const uint4* r1 = yin + (size_t)s1 * 6;
            uint4 a0 = r0[t];
            uint2 b0 = reinterpret_cast<const uint2*>(r0 + 4)[t];
            uint4 a1 = r1[t];
            uint2 b1 = reinterpret_cast<const uint2*>(r1 + 4)[t];
            acc_row(acc, a0, b0);
            acc_row(acc, a1, b1);
        }
        if (e < end) {
            int s0 = g_col[e];
            const uint4* r0 = yin + (size_t)s0 * 6;
            uint4 a0 = r0[t];
            uint2 b0 = reinterpret_cast<const uint2*>(r0 + 4)[t];
            acc_row(acc, a0, b0);
        }
    }
#pragma unroll
    for (int j = 0; j < 12; j++) acc[j] += __shfl_xor_sync(0xffffffffu, acc[j], 4);

    // ---- scale by 1/deg, add bias (identical in both quads) ----
    float di = g_dinv[n];
#pragma unroll
    for (int j = 0; j < 8; j++)  acc[j] = acc[j] * di + sb[t * 8 + j];
#pragma unroll
    for (int j = 0; j < 4; j++)  acc[8 + j] = acc[8 + j] * di + sb[32 + t * 4 + j];

    // ---- self transform, k-split across quads ----
    {
        float gacc[12];
#pragma unroll
        for (int j = 0; j < 12; j++) gacc[j] = 0.0f;
        const float4* xr =
            reinterpret_cast<const float4*>(xin + (size_t)n * KSELF) + q * (KSELF / 8);
#pragma unroll
        for (int k0 = 0; k0 < KSELF / 8; k0++) {
            float4 xv = xr[k0];
            float xs[4] = {xv.x, xv.y, xv.z, xv.w};
            int kb = q * (KSELF / 2) + k0 * 4;
#pragma unroll
            for (int kk = 0; kk < 4; kk++) {
                const float* wr = &sWs[(kb + kk) * H];
#pragma unroll
                for (int j = 0; j < 8; j++) gacc[j] += xs[kk] * wr[t * 8 + j];
#pragma unroll
                for (int j = 0; j < 4; j++) gacc[8 + j] += xs[kk] * wr[32 + t * 4 + j];
            }
        }
#pragma unroll
        for (int j = 0; j < 12; j++)
            gacc[j] += __shfl_xor_sync(0xffffffffu, gacc[j], 4);
#pragma unroll
        for (int j = 0; j < 12; j++) acc[j] = fmaxf(acc[j] + gacc[j], 0.0f);
    }
    // acc now holds h (identical across quads)

    if constexpr (!PRED) {
        if (valid && q == 0) {
            float* hr = hout + (size_t)g * H;
            float4* h4 = reinterpret_cast<float4*>(hr);
            h4[2 * t]     = make_float4(acc[0], acc[1], acc[2], acc[3]);
            h4[2 * t + 1] = make_float4(acc[4], acc[5], acc[6], acc[7]);
            reinterpret_cast<float4*>(hr + 32)[t] =
                make_float4(acc[8], acc[9], acc[10], acc[11]);
        }
        // ---- next neighbor transform y = h @ Wn, owner-pair split ----
        // quad q consumes h contributions from owner lanes {2q, 2q+1}
        float nacc[12];
#pragma unroll
        for (int j = 0; j < 12; j++) nacc[j] = 0.0f;
#pragma unroll
        for (int b = 0; b < 2; b++) {
            int lo = 2 * q + b;                    // source lane in quad 0
#pragma unroll
            for (int m = 0; m < 12; m++) {         // compile-time slot index
                float hk = __shfl_sync(0xffffffffu, acc[m], ob + lo);
                int k = (m < 8) ? (lo * 8 + m) : (32 + lo * 4 + (m - 8));
                const float* wr = &sWn[k * H];
#pragma unroll
                for (int j = 0; j < 8; j++) nacc[j] += hk * wr[t * 8 + j];
#pragma unroll
                for (int j = 0; j < 4; j++) nacc[8 + j] += hk * wr[32 + t * 4 + j];
            }
        }
#pragma unroll
        for (int j = 0; j < 12; j++)
            nacc[j] += __shfl_xor_sync(0xffffffffu, nacc[j], 4);
        if (valid && q == 0) {
            uint4* row = reinterpret_cast<uint4*>(yout_) + (size_t)g * 6;
            uint4 o;
            o.x = pack2(nacc[0], nacc[1]); o.y = pack2(nacc[2], nacc[3]);
            o.z = pack2(nacc[4], nacc[5]); o.w = pack2(nacc[6], nacc[7]);
            row[t] = o;
            reinterpret_cast<uint2*>(row + 4)[t] =
                make_uint2(pack2(nacc[8], nacc[9]), pack2(nacc[10], nacc[11]));
        }
    } else {
        // ---- prediction head (quads hold identical h; use quad-local reduce,
        //      only lane l==0 of each octet stores) ----
        float p = 0.0f;
#pragma unroll
        for (int j = 0; j < 8; j++) p += acc[j] * sWn[t * 8 + j];
#pragma unroll
        for (int j = 0; j < 4; j++) p += acc[8 + j] * sWn[32 + t * 4 + j];
        p += __shfl_down_sync(0xffffffffu, p, 1);
        p += __shfl_down_sync(0xffffffffu, p, 2);
        if (l == 0 && valid) reinterpret_cast<float*>(yout_)[g] = p + bn[0];

        // tail cleanup for next call
        if (gid < NN) g_deg[gid] = 0;
        if (gid == 0) g_alloc = 0;
    }
}

// ---------------------------------------------------------------------------
extern "C" void kernel_launch(void* const* d_in, const int* in_sizes, int n_in,
                              void* d_out, int out_size) {
    const float* x        = (const float*)d_in[0];
    const int*   edge     = (const int*)d_in[1];
    const float* w_self0  = (const float*)d_in[2];
    const float* w_neigh0 = (const float*)d_in[3];
    const float* b0       = (const float*)d_in[4];
    const float* w_self1  = (const float*)d_in[5];
    const float* w_neigh1 = (const float*)d_in[6];
    const float* b1       = (const float*)d_in[7];
    const float* w_self2  = (const float*)d_in[8];
    const float* w_neigh2 = (const float*)d_in[9];
    const float* b2       = (const float*)d_in[10];
    const float* w_pred   = (const float*)d_in[11];
    const float* b_pred   = (const float*)d_in[12];
    float* out = (float*)d_out;

    const int* src = edge;
    const int* dst = edge + NE;

    uint4 *y0, *y1;
    float *h0, *h1;
    cudaGetSymbolAddress((void**)&y0, g_y0);
    cudaGetSymbolAddress((void**)&y1, g_y1);
    cudaGetSymbolAddress((void**)&h0, g_h0);
    cudaGetSymbolAddress((void**)&h1, g_h1);

    // CSR build (no scan: arbitrary-order segment allocation)
    k_count<<<GFILL, 256>>>(dst);
    k_alloc<<<(NN + 255) / 256, 256>>>();
    k_fill_gemm<<<GFILL + GNODE8, 256>>>(src, dst, x, w_neigh0, y0);

    // Layer 0: h0 = relu(x@Ws0 + b0 + agg(y0)*dinv); y1 = h0 @ w_neigh1
    k_layer<F0, false><<<GNODE8, 256>>>(x,  y0, w_self0, b0, w_neigh1, nullptr, h0, y1);
    // Layer 1: h1 = relu(h0@Ws1 + b1 + agg(y1)*dinv); y0 = h1 @ w_neigh2
    k_layer<H,  false><<<GNODE8, 256>>>(h0, y1, w_self1, b1, w_neigh2, nullptr, h1, y0);
    // Layer 2 + head (+ state reset for next call)
    k_layer<H,  true ><<<GNODE8, 256>>>(h1, y0, w_self2, b2, w_pred,  b_pred, nullptr, out);
}

// round 5
// speedup vs baseline: 1.4625x; 1.4625x over previous
#include <cuda_runtime.h>
#include <cuda_fp16.h>

// GraphSAGENet: 50000 nodes, 800000 edges, feats 96 -> 48 -> 48 -> 48 -> 1
constexpr int NN = 50000;
constexpr int NE = 800000;
constexpr int F0 = 96;
constexpr int H  = 48;
constexpr int GFILL  = NE / 256;                // 3125
constexpr int GNODE  = (NN * 4 + 255) / 256;    // 782 (4 threads per node)
constexpr int GPLACE = (NN + 255) / 256;        // 196
constexpr int NBIN   = 64;

// Scratch (static device globals; zero-initialized at module load).
// g_deg / g_alloc / g_bincnt are re-zeroed at the tail of the last kernel.
__device__ uint4 g_y0[NN * 6];   // fp16 y rows: 48 halfs = 96 B = 6 uint4
__device__ uint4 g_y1[NN * 6];
__device__ float g_h0[NN * H];
__device__ float g_h1[NN * H];
__device__ int   g_deg[NN];
__device__ int   g_alloc;
__device__ int2  g_seg[NN];      // (start, deg)
__device__ float g_dinv[NN];
__device__ int   g_cursor[NN];
__device__ int   g_col[NE];
__device__ int   g_bincnt[NBIN];
__device__ int   g_bincur[NBIN];
__device__ int   g_perm[NN];     // nodes sorted by degree bucket

// fp16 pack/unpack helpers
__device__ __forceinline__ unsigned pack2(float a, float b) {
    __half2 h = __float22half2_rn(make_float2(a, b));
    return *reinterpret_cast<unsigned*>(&h);
}
__device__ __forceinline__ float2 up2(unsigned u) {
    __half2 h = *reinterpret_cast<__half2*>(&u);
    return __half22float2(h);
}
__device__ __forceinline__ void acc_row(float* acc, uint4 a, uint2 b) {
    float2 f;
    f = up2(a.x); acc[0] += f.x; acc[1]  += f.y;
    f = up2(a.y); acc[2] += f.x; acc[3]  += f.y;
    f = up2(a.z); acc[4] += f.x; acc[5]  += f.y;
    f = up2(a.w); acc[6] += f.x; acc[7]  += f.y;
    f = up2(b.x); acc[8] += f.x; acc[9]  += f.y;
    f = up2(b.y); acc[10] += f.x; acc[11] += f.y;
}

// Feature mapping: lane t owns feats [8t..8t+7] (slots 0..7)
//                  and feats [32+4t..32+4t+3] (slots 8..11)

// ---------------------------------------------------------------------------
// degree histogram (g_deg zero on entry; tail of k_layer<PRED> re-zeroes it)
// ---------------------------------------------------------------------------
__global__ void k_count(const int* __restrict__ dst) {
    int e = blockIdx.x * 256 + threadIdx.x;
    atomicAdd(&g_deg[dst[e]], 1);
}

// ---------------------------------------------------------------------------
// segment allocation (warp-aggregated) + degree-bin histogram (block-aggregated)
// ---------------------------------------------------------------------------
__global__ void k_alloc() {
    __shared__ int scnt[NBIN];
    if (threadIdx.x < NBIN) scnt[threadIdx.x] = 0;
    __syncthreads();

    int i = blockIdx.x * 256 + threadIdx.x;
    int lane = threadIdx.x & 31;
    int d = (i < NN) ? g_deg[i] : 0;

    // segment alloc via warp-scan + one global atomic per warp
    int s = d;
#pragma unroll
    for (int off = 1; off < 32; off <<= 1) {
        int t = __shfl_up_sync(0xffffffffu, s, off);
        if (lane >= off) s += t;
    }
    int total = __shfl_sync(0xffffffffu, s, 31);
    int base = 0;
    if (lane == 31) base = atomicAdd(&g_alloc, total);
    base = __shfl_sync(0xffffffffu, base, 31);
    int start = base + s - d;

    if (i < NN) {
        g_seg[i] = make_int2(start, d);
        g_cursor[i] = start;
        g_dinv[i] = 1.0f / (float)(d > 1 ? d : 1);
        atomicAdd(&scnt[d < NBIN - 1 ? d : NBIN - 1], 1);
    }
    __syncthreads();
    if (threadIdx.x < NBIN && scnt[threadIdx.x] > 0)
        atomicAdd(&g_bincnt[threadIdx.x], scnt[threadIdx.x]);
}

// ---------------------------------------------------------------------------
// exclusive scan of bin counts -> running cursors (64 threads, 1 block)
// ---------------------------------------------------------------------------
__global__ void k_binscan() {
    __shared__ int s[NBIN];
    int v = g_bincnt[threadIdx.x];
    s[threadIdx.x] = v;
    __syncthreads();
#pragma unroll
    for (int off = 1; off < NBIN; off <<= 1) {
        int t = (threadIdx.x >= off) ? s[threadIdx.x - off] : 0;
        __syncthreads();
        s[threadIdx.x] += t;
        __syncthreads();
    }
    g_bincur[threadIdx.x] = s[threadIdx.x] - v;   // exclusive
}

// ---------------------------------------------------------------------------
// Fused launch:
//   blocks [0, GFILL)                : CSR column fill
//   blocks [GFILL, GFILL+GNODE)      : y0 = x @ W_neigh0 (fp16 out, coalesced)
//   blocks [GFILL+GNODE, +GPLACE)    : degree-bucket placement -> g_perm
// All three are mutually independent.
// ---------------------------------------------------------------------------
__global__ void k_fill_gemm_place(const int* __restrict__ src,
                                  const int* __restrict__ dst,
                                  const float* __restrict__ x,
                                  const float* __restrict__ W,
                                  uint4* __restrict__ yout) {
    if (blockIdx.x < GFILL) {
        int e = blockIdx.x * 256 + threadIdx.x;
        int pos = atomicAdd(&g_cursor[dst[e]], 1);
        g_col[pos] = src[e];
        return;
    }

    if (blockIdx.x >= GFILL + GNODE) {
        // placement: block-aggregated cursor bump per bin
        __shared__ int scnt[NBIN];
        __shared__ int sbase[NBIN];
        if (threadIdx.x < NBIN) scnt[threadIdx.x] = 0;
        __syncthreads();
        int i = (blockIdx.x - GFILL - GNODE) * 256 + threadIdx.x;
        int bin = 0, r = 0;
        if (i < NN) {
            int d = g_seg[i].y;
            bin = d < NBIN - 1 ? d : NBIN - 1;
            r = atomicAdd(&scnt[bin], 1);
        }
        __syncthreads();
        if (threadIdx.x < NBIN && scnt[threadIdx.x] > 0)
            sbase[threadIdx.x] = atomicAdd(&g_bincur[threadIdx.x], scnt[threadIdx.x]);
        __syncthreads();
        if (i < NN) g_perm[sbase[bin] + r] = i;
        return;
    }

    // ---- y0 GEMM (unpermuted: no gather, no divergence here) ----
    __shared__ float sW[F0 * H];
    for (int i = threadIdx.x; i < F0 * H; i += 256) sW[i] = W[i];
    __syncthreads();

    int idx = (blockIdx.x - GFILL) * 256 + threadIdx.x;
    int g = idx >> 2;
    int t = idx & 3;
    if (g >= NN) return;

    float acc[12];
#pragma unroll
    for (int j = 0; j < 12; j++) acc[j] = 0.0f;

    const float4* xr = reinterpret_cast<const float4*>(x + (size_t)g * F0);
#pragma unroll 2
    for (int k0 = 0; k0 < F0 / 4; k0++) {
        float4 xv = xr[k0];
        float xs[4] = {xv.x, xv.y, xv.z, xv.w};
#pragma unroll
        for (int kk = 0; kk < 4; kk++) {
            const float* wr = &sW[(k0 * 4 + kk) * H];
#pragma unroll
            for (int j = 0; j < 8; j++) acc[j] += xs[kk] * wr[t * 8 + j];
#pragma unroll
            for (int j = 0; j < 4; j++) acc[8 + j] += xs[kk] * wr[32 + t * 4 + j];
        }
    }

    uint4* row = yout + (size_t)g * 6;
    uint4 o;
    o.x = pack2(acc[0], acc[1]); o.y = pack2(acc[2], acc[3]);
    o.z = pack2(acc[4], acc[5]); o.w = pack2(acc[6], acc[7]);
    row[t] = o;
    reinterpret_cast<uint2*>(row + 4)[t] =
        make_uint2(pack2(acc[8], acc[9]), pack2(acc[10], acc[11]));
}

// ---------------------------------------------------------------------------
// Fused layer (4 lanes/node, degree-sorted node order via g_perm):
//   agg = sum_{s in N(n)} y_in[s]  (fp16 gather, fp32 accumulate)
//   h   = relu(x @ Wself + b + agg*dinv)
//   !PRED: store h; y_out = h @ Wnext (h exchanged across 4 lanes via shfl)
//   PRED : out[n] = h . wpred + bpred; tail: zero g_deg/g_alloc/g_bincnt
// ---------------------------------------------------------------------------
template <int KSELF, bool PRED>
__global__ void k_layer(const float* __restrict__ xin,
                        const uint4* __restrict__ yin,
                        const float* __restrict__ Ws,
                        const float* __restrict__ bias,
                        const float* __restrict__ Wn,   // [H*H] or [H] if PRED
                        const float* __restrict__ bn,   // b_pred if PRED
                        float* __restrict__ hout,       // null if PRED
                        void* __restrict__ yout_) {     // uint4* y_next or float* out
    __shared__ float sWs[KSELF * H];
    __shared__ float sWn[PRED ? H : H * H];
    __shared__ float sb[H];
    for (int i = threadIdx.x; i < KSELF * H; i += 256) sWs[i] = Ws[i];
    for (int i = threadIdx.x; i < (PRED ? H : H * H); i += 256) sWn[i] = Wn[i];
    if (threadIdx.x < H) sb[threadIdx.x] = bias[threadIdx.x];
    __syncthreads();

    int gid = blockIdx.x * 256 + threadIdx.x;
    int g = gid >> 2;
    int t = gid & 3;
    bool valid = g < NN;
    int n = g_perm[valid ? g : NN - 1];   // degree-sorted -> warp-uniform loops

    float acc[12];
#pragma unroll
    for (int j = 0; j < 12; j++) acc[j] = 0.0f;

    // ---- gather-aggregate over in-neighbors (fp16 rows) ----
    int2 seg = g_seg[n];
    int e = seg.x, end = seg.x + seg.y;
    for (; e + 2 <= end; e += 2) {
        int s0 = g_col[e];
        int s1 = g_col[e + 1];
        const uint4* r0 = yin + (size_t)s0 * 6;
        const uint4* r1 = yin + (size_t)s1 * 6;
        uint4 a0 = r0[t];
        uint2 b0 = reinterpret_cast<const uint2*>(r0 + 4)[t];
        uint4 a1 = r1[t];
        uint2 b1 = reinterpret_cast<const uint2*>(r1 + 4)[t];
        acc_row(acc, a0, b0);
        acc_row(acc, a1, b1);
    }
    if (e < end) {
        int s0 = g_col[e];
        const uint4* r0 = yin + (size_t)s0 * 6;
        uint4 a0 = r0[t];
        uint2 b0 = reinterpret_cast<const uint2*>(r0 + 4)[t];
        acc_row(acc, a0, b0);
    }

    // ---- scale by 1/deg, add bias ----
    float di = g_dinv[n];
#pragma unroll
    for (int j = 0; j < 8; j++)  acc[j] = acc[j] * di + sb[t * 8 + j];
#pragma unroll
    for (int j = 0; j < 4; j++)  acc[8 + j] = acc[8 + j] * di + sb[32 + t * 4 + j];

    // ---- self transform: acc += x[n] @ Wself ----
    const float4* xr = reinterpret_cast<const float4*>(xin + (size_t)n * KSELF);
#pragma unroll 2
    for (int k0 = 0; k0 < KSELF / 4; k0++) {
        float4 xv = xr[k0];
        float xs[4] = {xv.x, xv.y, xv.z, xv.w};
#pragma unroll
        for (int kk = 0; kk < 4; kk++) {
            const float* wr = &sWs[(k0 * 4 + kk) * H];
#pragma unroll
            for (int j = 0; j < 8; j++) acc[j] += xs[kk] * wr[t * 8 + j];
#pragma unroll
            for (int j = 0; j < 4; j++) acc[8 + j] += xs[kk] * wr[32 + t * 4 + j];
        }
    }

    // ---- ReLU ----
#pragma unroll
    for (int j = 0; j < 12; j++) acc[j] = fmaxf(acc[j], 0.0f);

    if constexpr (!PRED) {
        if (valid) {
            float* hr = hout + (size_t)n * H;
            float4* h4 = reinterpret_cast<float4*>(hr);
            h4[2 * t]     = make_float4(acc[0], acc[1], acc[2], acc[3]);
            h4[2 * t + 1] = make_float4(acc[4], acc[5], acc[6], acc[7]);
            reinterpret_cast<float4*>(hr + 32)[t] =
                make_float4(acc[8], acc[9], acc[10], acc[11]);
        }
        // next neighbor transform: y_out = h @ Wnext (fp16 out)
        float nacc[12];
#pragma unroll
        for (int j = 0; j < 12; j++) nacc[j] = 0.0f;
        int baseLane = (threadIdx.x & 31) & ~3;
#pragma unroll 1
        for (int q = 0; q < 4; q++) {
#pragma unroll
            for (int m = 0; m < 12; m++) {
                float hk = __shfl_sync(0xffffffffu, acc[m], baseLane + q);
                int k = (m < 8) ? (q * 8 + m) : (32 + q * 4 + (m - 8));
                const float* wr = &sWn[k * H];
#pragma unroll
                for (int j = 0; j < 8; j++) nacc[j] += hk * wr[t * 8 + j];
#pragma unroll
                for (int j = 0; j < 4; j++) nacc[8 + j] += hk * wr[32 + t * 4 + j];
            }
        }
        if (valid) {
            uint4* row = reinterpret_cast<uint4*>(yout_) + (size_t)n * 6;
            uint4 o;
            o.x = pack2(nacc[0], nacc[1]); o.y = pack2(nacc[2], nacc[3]);
            o.z = pack2(nacc[4], nacc[5]); o.w = pack2(nacc[6], nacc[7]);
            row[t] = o;
            reinterpret_cast<uint2*>(row + 4)[t] =
                make_uint2(pack2(nacc[8], nacc[9]), pack2(nacc[10], nacc[11]));
        }
    } else {
        // prediction head
        float p = 0.0f;
#pragma unroll
        for (int j = 0; j < 8; j++) p += acc[j] * sWn[t * 8 + j];
#pragma unroll
        for (int j = 0; j < 4; j++) p += acc[8 + j] * sWn[32 + t * 4 + j];
        p += __shfl_down_sync(0xffffffffu, p, 1);
        p += __shfl_down_sync(0xffffffffu, p, 2);
        if (t == 0 && valid) reinterpret_cast<float*>(yout_)[n] = p + bn[0];

        // tail cleanup: restore zeroed state for the next call
        if (gid < NN) g_deg[gid] = 0;
        if (gid < NBIN) g_bincnt[gid] = 0;
        if (gid == 0) g_alloc = 0;
    }
}

// ---------------------------------------------------------------------------
extern "C" void kernel_launch(void* const* d_in, const int* in_sizes, int n_in,
                              void* d_out, int out_size) {
    const float* x        = (const float*)d_in[0];
    const int*   edge     = (const int*)d_in[1];
    const float* w_self0  = (const float*)d_in[2];
    const float* w_neigh0 = (const float*)d_in[3];
    const float* b0       = (const float*)d_in[4];
    const float* w_self1  = (const float*)d_in[5];
    const float* w_neigh1 = (const float*)d_in[6];
    const float* b1       = (const float*)d_in[7];
    const float* w_self2  = (const float*)d_in[8];
    const float* w_neigh2 = (const float*)d_in[9];
    const float* b2       = (const float*)d_in[10];
    const float* w_pred   = (const float*)d_in[11];
    const float* b_pred   = (const float*)d_in[12];
    float* out = (float*)d_out;

    const int* src = edge;
    const int* dst = edge + NE;

    uint4 *y0, *y1;
    float *h0, *h1;
    cudaGetSymbolAddress((void**)&y0, g_y0);
    cudaGetSymbolAddress((void**)&y1, g_y1);
    cudaGetSymbolAddress((void**)&h0, g_h0);
    cudaGetSymbolAddress((void**)&h1, g_h1);

    // CSR build + degree-bucket sort
    k_count<<<GFILL, 256>>>(dst);
    k_alloc<<<GPLACE, 256>>>();
    k_binscan<<<1, NBIN>>>();
    k_fill_gemm_place<<<GFILL + GNODE + GPLACE, 256>>>(src, dst, x, w_neigh0, y0);

    // Layer 0: h0 = relu(x@Ws0 + b0 + agg(y0)*dinv); y1 = h0 @ w_neigh1
    k_layer<F0, false><<<GNODE, 256>>>(x,  y0, w_self0, b0, w_neigh1, nullptr, h0, y1);
    // Layer 1: h1 = relu(h0@Ws1 + b1 + agg(y1)*dinv); y0 = h1 @ w_neigh2
    k_layer<H,  false><<<GNODE, 256>>>(h0, y1, w_self1, b1, w_neigh2, nullptr, h1, y0);
    // Layer 2 + head (+ state reset for next call)
    k_layer<H,  true ><<<GNODE, 256>>>(h1, y0, w_self2, b2, w_pred,  b_pred, nullptr, out);
}

// round 6
// speedup vs baseline: 1.8615x; 1.2728x over previous
#include <cuda_runtime.h>
#include <cuda_fp16.h>

// GraphSAGENet: 50000 nodes, 800000 edges, feats 96 -> 48 -> 48 -> 48 -> 1
constexpr int NN = 50000;
constexpr int NE = 800000;
constexpr int F0 = 96;
constexpr int H  = 48;
constexpr int NPAIR = NN / 2;                    // 25000 node pairs
constexpr int GFILL = NE / 256;                  // 3125
constexpr int GPAIR = (NPAIR * 4 + 255) / 256;   // 391 (4 lanes per pair-slot)
constexpr int GN    = (NN + 255) / 256;          // 196

// Scratch (static device globals; zero-initialized at module load).
// g_deg / g_alloc are re-zeroed at the tail of the last kernel each call.
__device__ uint4 g_y0[NN * 6];   // fp16 y rows: 48 halfs = 96 B = 6 uint4
__device__ uint4 g_y1[NN * 6];
__device__ float g_h0[NN * H];
__device__ float g_h1[NN * H];
__device__ int   g_deg[NN];
__device__ int   g_alloc;
__device__ int2  g_seg[NN];      // (start, deg)
__device__ float g_dinv[NN];
__device__ int   g_cursor[NN];
__device__ int   g_col[NE];

// fp16 pack/unpack helpers
__device__ __forceinline__ unsigned pack2(float a, float b) {
    __half2 h = __float22half2_rn(make_float2(a, b));
    return *reinterpret_cast<unsigned*>(&h);
}
__device__ __forceinline__ float2 up2(unsigned u) {
    __half2 h = *reinterpret_cast<__half2*>(&u);
    return __half22float2(h);
}
__device__ __forceinline__ void acc_row(float* acc, uint4 a, uint2 b) {
    float2 f;
    f = up2(a.x); acc[0] += f.x; acc[1]  += f.y;
    f = up2(a.y); acc[2] += f.x; acc[3]  += f.y;
    f = up2(a.z); acc[4] += f.x; acc[5]  += f.y;
    f = up2(a.w); acc[6] += f.x; acc[7]  += f.y;
    f = up2(b.x); acc[8] += f.x; acc[9]  += f.y;
    f = up2(b.y); acc[10] += f.x; acc[11] += f.y;
}

// Feature mapping: lane t owns feats [8t..8t+7] (slots 0..7)
//                  and feats [32+4t..32+4t+3] (slots 8..11)

__device__ __forceinline__ void store_y16(uint4* __restrict__ yout, int n, int t,
                                          const float* acc) {
    uint4* row = yout + (size_t)n * 6;
    uint4 o;
    o.x = pack2(acc[0], acc[1]); o.y = pack2(acc[2], acc[3]);
    o.z = pack2(acc[4], acc[5]); o.w = pack2(acc[6], acc[7]);
    row[t] = o;
    reinterpret_cast<uint2*>(row + 4)[t] =
        make_uint2(pack2(acc[8], acc[9]), pack2(acc[10], acc[11]));
}

// 2-node GEMM body: a0/a1 += x[n0/n1] @ W (W in shared, each W float feeds 2 FMA)
template <int K>
__device__ __forceinline__ void gemm2(const float* __restrict__ xin,
                                      const float* __restrict__ sW,
                                      int n0, int n1, int t,
                                      float* a0, float* a1) {
    const float4* xr0 = reinterpret_cast<const float4*>(xin + (size_t)n0 * K);
    const float4* xr1 = reinterpret_cast<const float4*>(xin + (size_t)n1 * K);
#pragma unroll 2
    for (int k0 = 0; k0 < K / 4; k0++) {
        float4 xv0 = xr0[k0];
        float4 xv1 = xr1[k0];
        float xs0[4] = {xv0.x, xv0.y, xv0.z, xv0.w};
        float xs1[4] = {xv1.x, xv1.y, xv1.z, xv1.w};
#pragma unroll
        for (int kk = 0; kk < 4; kk++) {
            const float* wr = &sW[(k0 * 4 + kk) * H];
#pragma unroll
            for (int j = 0; j < 8; j++) {
                float w = wr[t * 8 + j];
                a0[j] += xs0[kk] * w;
                a1[j] += xs1[kk] * w;
            }
#pragma unroll
            for (int j = 0; j < 4; j++) {
                float w = wr[32 + t * 4 + j];
                a0[8 + j] += xs0[kk] * w;
                a1[8 + j] += xs1[kk] * w;
            }
        }
    }
}

// gather-aggregate one node's in-neighbors (fp16 rows), unroll x2
__device__ __forceinline__ void gather(const uint4* __restrict__ yin,
                                       int n, int t, float* acc) {
    int2 seg = g_seg[n];
    int e = seg.x, end = seg.x + seg.y;
    for (; e + 2 <= end; e += 2) {
        int s0 = g_col[e];
        int s1 = g_col[e + 1];
        const uint4* r0 = yin + (size_t)s0 * 6;
        const uint4* r1 = yin + (size_t)s1 * 6;
        uint4 a0 = r0[t];
        uint2 b0 = reinterpret_cast<const uint2*>(r0 + 4)[t];
        uint4 a1 = r1[t];
        uint2 b1 = reinterpret_cast<const uint2*>(r1 + 4)[t];
        acc_row(acc, a0, b0);
        acc_row(acc, a1, b1);
    }
    if (e < end) {
        int s0 = g_col[e];
        const uint4* r0 = yin + (size_t)s0 * 6;
        uint4 a0 = r0[t];
        uint2 b0 = reinterpret_cast<const uint2*>(r0 + 4)[t];
        acc_row(acc, a0, b0);
    }
}

// ---------------------------------------------------------------------------
// degree histogram (g_deg zero on entry; tail of final kernel re-zeroes it)
// ---------------------------------------------------------------------------
__global__ void k_count(const int* __restrict__ dst) {
    int e = blockIdx.x * 256 + threadIdx.x;
    atomicAdd(&g_deg[dst[e]], 1);
}

// ---------------------------------------------------------------------------
// segment allocation: start = atomicAdd(g_alloc, deg), warp-aggregated
// ---------------------------------------------------------------------------
__global__ void k_alloc() {
    int i = blockIdx.x * 256 + threadIdx.x;
    int lane = threadIdx.x & 31;
    int d = (i < NN) ? g_deg[i] : 0;

    int s = d;
#pragma unroll
    for (int off = 1; off < 32; off <<= 1) {
        int t = __shfl_up_sync(0xffffffffu, s, off);
        if (lane >= off) s += t;
    }
    int total = __shfl_sync(0xffffffffu, s, 31);
    int base = 0;
    if (lane == 31) base = atomicAdd(&g_alloc, total);
    base = __shfl_sync(0xffffffffu, base, 31);
    int start = base + s - d;

    if (i < NN) {
        g_seg[i] = make_int2(start, d);
        g_cursor[i] = start;
        g_dinv[i] = 1.0f / (float)(d > 1 ? d : 1);
    }
}

// ---------------------------------------------------------------------------
// Fused: blocks [0,GFILL) fill CSR cols; blocks [GFILL,GFILL+GPAIR):
// y0 = x @ W_neigh0 (fp16 out, 2 nodes/thread)
// ---------------------------------------------------------------------------
__global__ void k_fill_gemm(const int* __restrict__ src,
                            const int* __restrict__ dst,
                            const float* __restrict__ x,
                            const float* __restrict__ W,
                            uint4* __restrict__ yout) {
    __shared__ float sW[F0 * H];

    if (blockIdx.x < GFILL) {
        int e = blockIdx.x * 256 + threadIdx.x;
        int pos = atomicAdd(&g_cursor[dst[e]], 1);
        g_col[pos] = src[e];
        return;
    }

    for (int i = threadIdx.x; i < F0 * H; i += 256) sW[i] = W[i];
    __syncthreads();

    int idx = (blockIdx.x - GFILL) * 256 + threadIdx.x;
    int p = idx >> 2;
    int t = idx & 3;
    if (p >= NPAIR) return;
    int n0 = 2 * p, n1 = 2 * p + 1;

    float a0[12], a1[12];
#pragma unroll
    for (int j = 0; j < 12; j++) { a0[j] = 0.0f; a1[j] = 0.0f; }

    gemm2<F0>(x, sW, n0, n1, t, a0, a1);

    store_y16(yout, n0, t, a0);
    store_y16(yout, n1, t, a1);
}

// ---------------------------------------------------------------------------
// Standalone next-neighbor GEMM: y = h @ W (fp16 out, 2 nodes/thread)
// ---------------------------------------------------------------------------
__global__ void k_gemm(const float* __restrict__ hin,
                       const float* __restrict__ W,
                       uint4* __restrict__ yout) {
    __shared__ float sW[H * H];
    for (int i = threadIdx.x; i < H * H; i += 256) sW[i] = W[i];
    __syncthreads();

    int idx = blockIdx.x * 256 + threadIdx.x;
    int p = idx >> 2;
    int t = idx & 3;
    if (p >= NPAIR) return;
    int n0 = 2 * p, n1 = 2 * p + 1;

    float a0[12], a1[12];
#pragma unroll
    for (int j = 0; j < 12; j++) { a0[j] = 0.0f; a1[j] = 0.0f; }

    gemm2<H>(hin, sW, n0, n1, t, a0, a1);

    store_y16(yout, n0, t, a0);
    store_y16(yout, n1, t, a1);
}

// ---------------------------------------------------------------------------
// Layer kernel (2 nodes/thread, 4 lanes per node-pair slot):
//   agg_i = sum_{s in N(n_i)} y_in[s]; h_i = relu(x[n_i]@Wself + b + agg_i*dinv)
//   !PRED: store h_i ; PRED: out[n_i] = h_i . wpred + bpred (+ state reset)
// ---------------------------------------------------------------------------
template <int KSELF, bool PRED>
__global__ void k_layer(const float* __restrict__ xin,
                        const uint4* __restrict__ yin,
                        const float* __restrict__ Ws,
                        const float* __restrict__ bias,
                        const float* __restrict__ wp,   // pred weights (PRED)
                        const float* __restrict__ bp,   // pred bias (PRED)
                        float* __restrict__ hout,       // h out (!PRED)
                        float* __restrict__ outp) {     // pred out (PRED)
    __shared__ float sWs[KSELF * H];
    __shared__ float sb[H];
    __shared__ float sWp[H];
    for (int i = threadIdx.x; i < KSELF * H; i += 256) sWs[i] = Ws[i];
    if (threadIdx.x < H) {
        sb[threadIdx.x] = bias[threadIdx.x];
        if constexpr (PRED) sWp[threadIdx.x] = wp[threadIdx.x];
    }
    __syncthreads();

    int gid = blockIdx.x * 256 + threadIdx.x;

    if constexpr (PRED) {   // state reset for next call (no reads here)
        if (gid < NN) g_deg[gid] = 0;
        if (gid == 0) g_alloc = 0;
    }

    int p = gid >> 2;
    int t = gid & 3;
    if (p >= NPAIR) return;   // warp-aligned exit (NPAIR*4 divisible by 32)
    int n0 = 2 * p, n1 = 2 * p + 1;

    float a0[12], a1[12];
#pragma unroll
    for (int j = 0; j < 12; j++) { a0[j] = 0.0f; a1[j] = 0.0f; }

    // ---- gather both nodes ----
    gather(yin, n0, t, a0);
    gather(yin, n1, t, a1);

    // ---- scale by 1/deg, add bias ----
    float d0 = g_dinv[n0];
    float d1 = g_dinv[n1];
#pragma unroll
    for (int j = 0; j < 8; j++) {
        float b = sb[t * 8 + j];
        a0[j] = a0[j] * d0 + b;
        a1[j] = a1[j] * d1 + b;
    }
#pragma unroll
    for (int j = 0; j < 4; j++) {
        float b = sb[32 + t * 4 + j];
        a0[8 + j] = a0[8 + j] * d0 + b;
        a1[8 + j] = a1[8 + j] * d1 + b;
    }

    // ---- self transform (shared W float feeds 2 FMA) ----
    gemm2<KSELF>(xin, sWs, n0, n1, t, a0, a1);

    // ---- ReLU ----
#pragma unroll
    for (int j = 0; j < 12; j++) {
        a0[j] = fmaxf(a0[j], 0.0f);
        a1[j] = fmaxf(a1[j], 0.0f);
    }

    if constexpr (!PRED) {
        float* h0 = hout + (size_t)n0 * H;
        float* h1 = hout + (size_t)n1 * H;
        float4* h40 = reinterpret_cast<float4*>(h0);
        float4* h41 = reinterpret_cast<float4*>(h1);
        h40[2 * t]     = make_float4(a0[0], a0[1], a0[2], a0[3]);
        h40[2 * t + 1] = make_float4(a0[4], a0[5], a0[6], a0[7]);
        reinterpret_cast<float4*>(h0 + 32)[t] =
            make_float4(a0[8], a0[9], a0[10], a0[11]);
        h41[2 * t]     = make_float4(a1[0], a1[1], a1[2], a1[3]);
        h41[2 * t + 1] = make_float4(a1[4], a1[5], a1[6], a1[7]);
        reinterpret_cast<float4*>(h1 + 32)[t] =
            make_float4(a1[8], a1[9], a1[10], a1[11]);
    } else {
        // prediction head for both nodes
        float p0 = 0.0f, p1 = 0.0f;
#pragma unroll
        for (int j = 0; j < 8; j++) {
            float w = sWp[t * 8 + j];
            p0 += a0[j] * w;
            p1 += a1[j] * w;
        }
#pragma unroll
        for (int j = 0; j < 4; j++) {
            float w = sWp[32 + t * 4 + j];
            p0 += a0[8 + j] * w;
            p1 += a1[8 + j] * w;
        }
        p0 += __shfl_down_sync(0xffffffffu, p0, 1);
        p0 += __shfl_down_sync(0xffffffffu, p0, 2);
        p1 += __shfl_down_sync(0xffffffffu, p1, 1);
        p1 += __shfl_down_sync(0xffffffffu, p1, 2);
        if (t == 0) {
            float bb = bp[0];
            outp[n0] = p0 + bb;
            outp[n1] = p1 + bb;
        }
    }
}

// ---------------------------------------------------------------------------
extern "C" void kernel_launch(void* const* d_in, const int* in_sizes, int n_in,
                              void* d_out, int out_size) {
    const float* x        = (const float*)d_in[0];
    const int*   edge     = (const int*)d_in[1];
    const float* w_self0  = (const float*)d_in[2];
    const float* w_neigh0 = (const float*)d_in[3];
    const float* b0       = (const float*)d_in[4];
    const float* w_self1  = (const float*)d_in[5];
    const float* w_neigh1 = (const float*)d_in[6];
    const float* b1       = (const float*)d_in[7];
    const float* w_self2  = (const float*)d_in[8];
    const float* w_neigh2 = (const float*)d_in[9];
    const float* b2       = (const float*)d_in[10];
    const float* w_pred   = (const float*)d_in[11];
    const float* b_pred   = (const float*)d_in[12];
    float* out = (float*)d_out;

    const int* src = edge;
    const int* dst = edge + NE;

    uint4 *y0, *y1;
    float *h0, *h1;
    cudaGetSymbolAddress((void**)&y0, g_y0);
    cudaGetSymbolAddress((void**)&y1, g_y1);
    cudaGetSymbolAddress((void**)&h0, g_h0);
    cudaGetSymbolAddress((void**)&h1, g_h1);

    // CSR build
    k_count<<<GFILL, 256>>>(dst);
    k_alloc<<<GN, 256>>>();
    k_fill_gemm<<<GFILL + GPAIR, 256>>>(src, dst, x, w_neigh0, y0);

    // Layer 0: h0 = relu(x@Ws0 + b0 + agg(y0)*dinv)
    k_layer<F0, false><<<GPAIR, 256>>>(x, y0, w_self0, b0, nullptr, nullptr, h0, nullptr);
    // y1 = h0 @ w_neigh1
    k_gemm<<<GPAIR, 256>>>(h0, w_neigh1, y1);
    // Layer 1: h1 = relu(h0@Ws1 + b1 + agg(y1)*dinv)
    k_layer<H, false><<<GPAIR, 256>>>(h0, y1, w_self1, b1, nullptr, nullptr, h1, nullptr);
    // y0 = h1 @ w_neigh2
    k_gemm<<<GPAIR, 256>>>(h1, w_neigh2, y0);
    // Layer 2 + head (+ state reset for next call)
    k_layer<H, true><<<GPAIR, 256>>>(h1, y0, w_self2, b2, w_pred, b_pred, nullptr, out);
}